// round 12
// baseline (speedup 1.0000x reference)
#include <cuda_runtime.h>
#include <cuda_fp16.h>
#include <math.h>
#include <stdint.h>

#define BATCH 32768
#define DIM   256
#define CBK   1024
#define LVL   8
#define BM    128
#define GRID  (BATCH / BM)           // 256
#define MUT   1.2e-3f                // = 2*B, B >= hard fp16 single-pass score-error bound

// smem byte offsets
#define SO_A    0                    // A tile [128 rows][256 k] fp16, 512B rows = 65536
#define SO_B    65536                // B slabs 2 x [128 codes][128 k] fp16 = 65536
#define SO_EE   131072               // 1024 floats
#define SO_CV   135168               // cand values [128 rows][32] = 16384
#define SO_CI   151552               // cand indices = 16384
#define SO_IDX  167936               // 128 ints
#define SO_RED  168448               // 512 floats
#define SO_CNT  170496               // [0]=rescue cnt, [1]=fullscan cnt (+pad)
#define SO_WV   170512               // 16 floats (block argmin)
#define SO_WI   170576               // 16 ints
#define SO_RQ   170640               // 128 entries x 6 ints = 3072
#define SO_FQ   173712               // 128 ints
#define SMEM_BYTES 174224

// ---------------- device scratch ----------------
__device__ float g_resid[BATCH * DIM];
__device__ float g_qsum [BATCH * DIM];
__device__ float g_xx   [BATCH];
__device__ float g_ee   [LVL * CBK];
__device__ int   g_idx  [BATCH * LVL];
__device__ float g_commit_part[LVL * GRID];
__device__ int   g_counts[CBK];
__device__ __half g_ah[BATCH * DIM];        // residual fp16
__device__ __half g_bh[LVL * CBK * DIM];    // codebook fp16

// ---------------- helpers ----------------
__device__ __forceinline__ uint32_t smem_u32(const void* p) {
    uint32_t a;
    asm("{ .reg .u64 t; cvta.to.shared.u64 t, %1; cvt.u32.u64 %0, t; }" : "=r"(a) : "l"(p));
    return a;
}
#define CP16(dst, src) asm volatile("cp.async.cg.shared.global [%0], [%1], 16;" :: "r"(dst), "l"(src))
#define CPCOMMIT()     asm volatile("cp.async.commit_group;" ::: "memory")
#define CPWAIT1()      asm volatile("cp.async.wait_group 1;" ::: "memory")
#define CPWAIT0()      asm volatile("cp.async.wait_group 0;" ::: "memory")

__device__ __forceinline__ void ldsm_x4(uint32_t* r, uint32_t addr) {
    asm volatile("ldmatrix.sync.aligned.m8n8.x4.shared.b16 {%0,%1,%2,%3}, [%4];"
        : "=r"(r[0]), "=r"(r[1]), "=r"(r[2]), "=r"(r[3]) : "r"(addr));
}
__device__ __forceinline__ void mma_f16(float* d, const uint32_t* a, const uint32_t* b) {
    asm volatile("mma.sync.aligned.m16n8k16.row.col.f32.f16.f16.f32 "
        "{%0,%1,%2,%3}, {%4,%5,%6,%7}, {%8,%9}, {%0,%1,%2,%3};"
        : "+f"(d[0]), "+f"(d[1]), "+f"(d[2]), "+f"(d[3])
        : "r"(a[0]), "r"(a[1]), "r"(a[2]), "r"(a[3]), "r"(b[0]), "r"(b[1]));
}

// ---------------- prep kernels ----------------
__global__ void k_prepB(const float* __restrict__ emb)
{
    int i = blockIdx.x * blockDim.x + threadIdx.x;
    if (i >= LVL * CBK * DIM) return;
    g_bh[i] = __float2half_rn(emb[i]);
}

__global__ void k_eeinit(const float* __restrict__ emb)
{
    int gt = blockIdx.x * blockDim.x + threadIdx.x;
    if (gt < CBK) g_counts[gt] = 0;
    int gw   = blockIdx.x * (blockDim.x >> 5) + (threadIdx.x >> 5);
    int lane = threadIdx.x & 31;
    if (gw >= LVL * CBK) return;
    const float* r = emb + (size_t)gw * DIM;
    float s = 0.f;
#pragma unroll
    for (int j = 0; j < 8; j++) { float v = r[lane + 32 * j]; s = fmaf(v, v, s); }
#pragma unroll
    for (int o = 16; o; o >>= 1) s += __shfl_xor_sync(0xffffffffu, s, o);
    if (!lane) g_ee[gw] = s;
}

__global__ void k_prepA(const float* __restrict__ z)
{
    int gw   = blockIdx.x * (blockDim.x >> 5) + (threadIdx.x >> 5);
    int lane = threadIdx.x & 31;
    if (gw >= BATCH) return;
    const float* r = z + (size_t)gw * DIM;
    float s = 0.f;
#pragma unroll
    for (int j = 0; j < 8; j++) {
        float v = r[lane + 32 * j];
        g_ah[(size_t)gw * DIM + lane + 32 * j] = __float2half_rn(v);
        s = fmaf(v, v, s);
    }
#pragma unroll
    for (int o = 16; o; o >>= 1) s += __shfl_xor_sync(0xffffffffu, s, o);
    if (!lane) g_xx[gw] = s;
}

// ---------------- main per-level kernel: fp16 1-pass HMMA + provable 3-way ----------
// 256 CTAs x 512 threads (16 warps = 4m x 4n, warp tile 32x32, acc 32 regs).
// Per-lane top-2 over its 64 codes -> 32 candidates/row in smem (no lossy merge).
// Guard G = min lane-group v2 lower-bounds uncaptured candidates.
// Decision: direct / <=4-candidate exact rescue / full 1024-code exact scan.
__global__ void __launch_bounds__(512, 1)
k_level(const float* __restrict__ z,
        const float* __restrict__ cb,     // fp32 codebook for this level
        int level,
        float* __restrict__ o_idx_f)
{
    extern __shared__ char smem[];
    uint32_t sb = smem_u32(smem);
    float* ee_s  = (float*)(smem + SO_EE);
    float* cv    = (float*)(smem + SO_CV);
    int*   cidx  = (int*)(smem + SO_CI);
    int*   s_idx = (int*)(smem + SO_IDX);
    float* s_red = (float*)(smem + SO_RED);
    int*   s_cnt = (int*)(smem + SO_CNT);      // [0]=rescue, [1]=fullscan
    float* wv    = (float*)(smem + SO_WV);
    int*   wi    = (int*)(smem + SO_WI);
    int*   rq    = (int*)(smem + SO_RQ);
    int*   fq    = (int*)(smem + SO_FQ);

    const int tid = threadIdx.x, wid = tid >> 5, lane = tid & 31;
    const int wm = wid >> 2, wn = wid & 3;
    const int row0 = blockIdx.x * BM;
    const int first = (level == 0);
    const float* A_src = first ? z : g_resid;
    const __half* pbh = g_bh + (size_t)level * CBK * DIM;

    if (tid == 0) { s_cnt[0] = 0; s_cnt[1] = 0; }

    // ---- A tile: [128 rows][256 k] fp16, 512B rows, swizzled, cp.async ----
    {
#pragma unroll
        for (int i = 0; i < 8; i++) {
            int ch = i * 512 + tid;                    // 4096 chunks of 16B
            int m = ch >> 5, kc = ch & 31;
            const __half* src = g_ah + (size_t)(row0 + m) * DIM + kc * 8;
            uint32_t dst = sb + SO_A + m * 512 + ((kc * 16) ^ ((m & 7) << 4));
            CP16(dst, src);
        }
        CPCOMMIT();
    }
    for (int i = tid; i < CBK; i += 512) ee_s[i] = g_ee[level * CBK + i];

    const int q2   = (lane & 3) * 2;
    const int rthr = lane >> 2;
    const int arow = ((lane >> 3) & 1) * 8 + (lane & 7);
    const int kofA = (lane >> 4) * 8;
    const int brow = ((lane >> 4) & 1) * 8 + (lane & 7);
    const int kofB = ((lane >> 3) & 1) * 8;

    uint32_t aOff[2]; int aKey[2];
#pragma unroll
    for (int im = 0; im < 2; im++) {
        int m = wm * 32 + im * 16 + arow;
        aOff[im] = sb + SO_A + m * 512;
        aKey[im] = (m & 7) << 4;
    }
    uint32_t bOff[2]; int bKey[2];
#pragma unroll
    for (int jg = 0; jg < 2; jg++) {
        int nr = wn * 32 + jg * 16 + brow;
        bOff[jg] = nr * 256;
        bKey[jg] = (nr & 7) << 4;
    }
    float xr[4];
#pragma unroll
    for (int i = 0; i < 4; i++)
        xr[i] = g_xx[row0 + wm * 32 + (i >> 1) * 16 + (i & 1) * 8 + rthr];

    float acc[2][4][4];
#pragma unroll
    for (int a = 0; a < 2; a++)
#pragma unroll
        for (int b = 0; b < 4; b++)
#pragma unroll
            for (int c = 0; c < 4; c++) acc[a][b][c] = 0.f;
    float v1[4], v2[4]; int i1[4], i2[4];
#pragma unroll
    for (int i = 0; i < 4; i++) { v1[i] = 3.4e38f; v2[i] = 3.4e38f; i1[i] = 1 << 29; i2[i] = 1 << 29; }

    // B slab s: codes [nt*128,+128), k [half*128,+128); 32KB, 256B swizzled rows
    auto loadB = [&](int s) {
        int nt = s >> 1, half = s & 1;
        uint32_t dB = sb + SO_B + (s & 1) * 32768;
#pragma unroll
        for (int i = 0; i < 4; i++) {
            int ch = i * 512 + tid;
            int r = ch >> 4, kc = ch & 15;
            CP16(dB + r * 256 + ((kc * 16) ^ ((r & 7) << 4)),
                 pbh + (size_t)(nt * 128 + r) * DIM + half * 128 + kc * 8);
        }
        CPCOMMIT();
    };

    loadB(0);

#define UPD(rp, dval, cidx2) do { \
        if ((dval) < v1[rp]) { v2[rp] = v1[rp]; i2[rp] = i1[rp]; v1[rp] = (dval); i1[rp] = (cidx2); } \
        else if ((dval) < v2[rp]) { v2[rp] = (dval); i2[rp] = (cidx2); } } while (0)

    // ---- mainloop: 8 N-chunks x 2 k-halves = 16 steps ----
    for (int s = 0; s < 16; s++) {
        if (s + 1 < 16) { loadB(s + 1); CPWAIT1(); } else { CPWAIT0(); }
        __syncthreads();
        int nt = s >> 1, half = s & 1;
        uint32_t bB = sb + SO_B + (s & 1) * 32768;
#pragma unroll
        for (int kc = 0; kc < 8; kc++) {
            uint32_t bf[2][4];
#pragma unroll
            for (int jg = 0; jg < 2; jg++)
                ldsm_x4(bf[jg], bB + bOff[jg] + ((((kc * 16 + kofB) << 1)) ^ bKey[jg]));
            uint32_t af[2][4];
            int kh = half * 128 + kc * 16;
#pragma unroll
            for (int im = 0; im < 2; im++)
                ldsm_x4(af[im], aOff[im] + ((((kh + kofA) << 1)) ^ aKey[im]));
#pragma unroll
            for (int im = 0; im < 2; im++) {
                mma_f16(acc[im][0], af[im], &bf[0][0]);
                mma_f16(acc[im][1], af[im], &bf[0][2]);
                mma_f16(acc[im][2], af[im], &bf[1][0]);
                mma_f16(acc[im][3], af[im], &bf[1][2]);
            }
        }
        if (half) {                                     // N-chunk done: score + top-2
#pragma unroll
            for (int im = 0; im < 2; im++)
#pragma unroll
                for (int jj = 0; jj < 4; jj++) {
                    int col = nt * 128 + wn * 32 + (jj >> 1) * 16 + (jj & 1) * 8 + q2;
                    float e0 = ee_s[col], e1 = ee_s[col + 1];
                    float d;
                    d = (xr[im * 2] + e0) - 2.0f * acc[im][jj][0];
                    UPD(im * 2, d, col);
                    d = (xr[im * 2] + e1) - 2.0f * acc[im][jj][1];
                    UPD(im * 2, d, col + 1);
                    d = (xr[im * 2 + 1] + e0) - 2.0f * acc[im][jj][2];
                    UPD(im * 2 + 1, d, col);
                    d = (xr[im * 2 + 1] + e1) - 2.0f * acc[im][jj][3];
                    UPD(im * 2 + 1, d, col + 1);
                    acc[im][jj][0] = 0.f; acc[im][jj][1] = 0.f;
                    acc[im][jj][2] = 0.f; acc[im][jj][3] = 0.f;
                }
        }
        __syncthreads();
    }

    // ---- every lane stores its own top-2 (16 lane-groups x 2 per row, lossless) ----
#pragma unroll
    for (int i = 0; i < 4; i++) {
        int row = wm * 32 + (i >> 1) * 16 + (i & 1) * 8 + rthr;
        int g = (wn * 4 + (lane & 3)) * 2;
        cv[row * 32 + g]     = v1[i];  cidx[row * 32 + g]     = i1[i];
        cv[row * 32 + g + 1] = v2[i];  cidx[row * 32 + g + 1] = i2[i];
    }
    __syncthreads();

    // ---- per-row decision (thread tid = row): direct / rescue / full-scan ----
    if (tid < 128) {
        float w0 = 3.4e38f; int x0 = 1 << 30; float G = 3.4e38f;
#pragma unroll
        for (int g2 = 0; g2 < 32; g2++) {
            float v = cv[tid * 32 + g2];
            int  ix = cidx[tid * 32 + g2];
            if (v < w0 || (v == w0 && ix < x0)) { w0 = v; x0 = ix; }
            if (g2 & 1) G = fminf(G, v);       // lane-group v2 entries
        }
        float T = w0 + MUT;
        if (G <= T) {
            fq[atomicAdd(&s_cnt[1], 1)] = tid;              // uncaptured may be in margin
        } else {
            int n = 0, cand[4];
#pragma unroll
            for (int g2 = 0; g2 < 32; g2++) {
                float v = cv[tid * 32 + g2];
                if (v <= T) { if (n < 4) cand[n] = cidx[tid * 32 + g2]; n++; }
            }
            if (n > 4) {
                fq[atomicAdd(&s_cnt[1], 1)] = tid;
            } else if (n == 1) {                            // provably the reference winner
                s_idx[tid] = x0;
                int gr = row0 + tid;
                g_idx[(size_t)gr * LVL + level] = x0;
                if (o_idx_f) o_idx_f[(size_t)gr * LVL + level] = (float)x0;
            } else {                                        // exact rescue among n cands
                int pos = atomicAdd(&s_cnt[0], 1);
                rq[pos * 6 + 0] = tid;
                rq[pos * 6 + 1] = n;
#pragma unroll
                for (int q = 0; q < 4; q++) rq[pos * 6 + 2 + q] = (q < n) ? cand[q] : 0;
            }
        }
    }
    __syncthreads();

    // ---- rescue: exact fp32 sequential-k dd for <=4 candidates (warp per entry) ----
    {
        int cnt = s_cnt[0];
        for (int e = wid; e < cnt; e += 16) {
            int row = rq[e * 6], n = rq[e * 6 + 1];
            float dd = 3.4e38f; int ci = 1 << 30;
            if (lane < n) {
                ci = rq[e * 6 + 2 + lane];
                const float* a  = A_src + (size_t)(row0 + row) * DIM;
                const float* ep = cb + (size_t)ci * DIM;
                float dot = 0.f;
#pragma unroll 4
                for (int k = 0; k < 256; k++) dot = fmaf(a[k], ep[k], dot);
                dd = (g_xx[row0 + row] + ee_s[ci]) - 2.0f * dot;
            }
#pragma unroll
            for (int o = 1; o <= 2; o <<= 1) {
                float ov = __shfl_xor_sync(0xffffffffu, dd, o);
                int   oi = __shfl_xor_sync(0xffffffffu, ci, o);
                if (ov < dd || (ov == dd && oi < ci)) { dd = ov; ci = oi; }
            }
            if (lane == 0) {
                s_idx[row] = ci;
                int gr = row0 + row;
                g_idx[(size_t)gr * LVL + level] = ci;
                if (o_idx_f) o_idx_f[(size_t)gr * LVL + level] = (float)ci;
            }
        }
    }
    __syncthreads();

    // ---- full-scan: exact 1024-code scan by whole CTA (rare; uniform control flow) ----
    {
        int fcnt = s_cnt[1];
        for (int e = 0; e < fcnt; e++) {
            int row = fq[e];
            const float* a = A_src + (size_t)(row0 + row) * DIM;
            float xxv = g_xx[row0 + row];
            float best = 3.4e38f; int bix = 1 << 30;
            for (int c = tid; c < CBK; c += 512) {
                const float* ep = cb + (size_t)c * DIM;
                float dot = 0.f;
#pragma unroll 4
                for (int k = 0; k < 256; k++) dot = fmaf(a[k], ep[k], dot);
                float dd = (xxv + ee_s[c]) - 2.0f * dot;
                if (dd < best || (dd == best && c < bix)) { best = dd; bix = c; }
            }
#pragma unroll
            for (int o = 16; o; o >>= 1) {
                float ov = __shfl_xor_sync(0xffffffffu, best, o);
                int   oi = __shfl_xor_sync(0xffffffffu, bix, o);
                if (ov < best || (ov == best && oi < bix)) { best = ov; bix = oi; }
            }
            if (!lane) { wv[wid] = best; wi[wid] = bix; }
            __syncthreads();
            if (tid == 0) {
                float b2 = wv[0]; int bi2 = wi[0];
                for (int w2 = 1; w2 < 16; w2++)
                    if (wv[w2] < b2 || (wv[w2] == b2 && wi[w2] < bi2)) { b2 = wv[w2]; bi2 = wi[w2]; }
                s_idx[row] = bi2;
                int gr = row0 + row;
                g_idx[(size_t)gr * LVL + level] = bi2;
                if (o_idx_f) o_idx_f[(size_t)gr * LVL + level] = (float)bi2;
            }
            __syncthreads();
        }
    }
    __syncthreads();

    // ---- fused epilogue: residual, qsum, fp16 for next level, xx, commit ----
    {
        int r4 = tid >> 2, dq = (tid & 3) << 6;     // 4 threads/row, 64 dims each
        int gi = s_idx[r4];
        const float* ev = cb + (size_t)gi * DIM + dq;
        size_t gofs = (size_t)(row0 + r4) * DIM + dq;
        const float* av = A_src + gofs;
        float* ro = g_resid + gofs;
        float* qo = g_qsum + gofs;
        __half2* ho = (__half2*)(g_ah + gofs);
        float ss = 0.f;
#pragma unroll 4
        for (int j = 0; j < 16; j++) {
            float4 a = *(const float4*)(av + j * 4);
            float4 e = *(const float4*)(ev + j * 4);
            float4 rn = make_float4(a.x - e.x, a.y - e.y, a.z - e.z, a.w - e.w);
            *(float4*)(ro + j * 4) = rn;
            float4 q;
            if (first) q = e;
            else {
                float4 qp = *(const float4*)(qo + j * 4);
                q = make_float4(qp.x + e.x, qp.y + e.y, qp.z + e.z, qp.w + e.w);
            }
            *(float4*)(qo + j * 4) = q;
            ho[j * 2]     = __floats2half2_rn(rn.x, rn.y);
            ho[j * 2 + 1] = __floats2half2_rn(rn.z, rn.w);
            ss = fmaf(rn.x, rn.x, ss); ss = fmaf(rn.y, rn.y, ss);
            ss = fmaf(rn.z, rn.z, ss); ss = fmaf(rn.w, rn.w, ss);
        }
        s_red[tid] = ss;
        __syncthreads();
        if (!(tid & 3))
            g_xx[row0 + r4] = (s_red[tid] + s_red[tid + 1]) + (s_red[tid + 2] + s_red[tid + 3]);
        __syncthreads();
#pragma unroll
        for (int o = 256; o; o >>= 1) {
            if (tid < o) s_red[tid] += s_red[tid + o];
            __syncthreads();
        }
        if (!tid) g_commit_part[level * GRID + blockIdx.x] = s_red[0];
    }
#undef UPD
}

// ---------------- histogram ----------------
__global__ void k_count()
{
    __shared__ int h[CBK];
    for (int i = threadIdx.x; i < CBK; i += blockDim.x) h[i] = 0;
    __syncthreads();
    int stride = gridDim.x * blockDim.x;
    for (int i = blockIdx.x * blockDim.x + threadIdx.x; i < BATCH * LVL; i += stride)
        atomicAdd(&h[g_idx[i]], 1);
    __syncthreads();
    for (int i = threadIdx.x; i < CBK; i += blockDim.x) {
        int v = h[i];
        if (v) atomicAdd(&g_counts[i], v);
    }
}

// ---------------- z_q ----------------
__global__ void k_zq(const float* __restrict__ z, float* __restrict__ out)
{
    int n = BATCH * DIM / 4;
    for (int i = blockIdx.x * blockDim.x + threadIdx.x; i < n; i += gridDim.x * blockDim.x) {
        float4 zv = ((const float4*)z)[i];
        float4 qv = ((const float4*)g_qsum)[i];
        float4 t = make_float4(qv.x - zv.x, qv.y - zv.y, qv.z - zv.z, qv.w - zv.w);
        ((float4*)out)[i] = make_float4(zv.x + t.x, zv.y + t.y, zv.z + t.z, zv.w + t.w);
    }
}

// ---------------- scalars ----------------
__global__ void k_final(float* __restrict__ o_sc)
{
    __shared__ float se[1024];
    __shared__ float sc[LVL];
    int t = threadIdx.x;
    float p = (float)g_counts[t] / 262144.0f;
    se[t] = (p > 0.f) ? p * logf(p + 1e-10f) : 0.f;
    __syncthreads();
#pragma unroll
    for (int o = 512; o; o >>= 1) {
        if (t < o) se[t] += se[t + o];
        __syncthreads();
    }
    int w = t >> 5, lane = t & 31;
    if (w < LVL) {
        float s = 0.f;
        for (int b = lane; b < GRID; b += 32) s += g_commit_part[w * GRID + b];
#pragma unroll
        for (int o = 16; o; o >>= 1) s += __shfl_xor_sync(0xffffffffu, s, o);
        if (!lane) sc[w] = s;
    }
    __syncthreads();
    if (!t && o_sc) {
        float ent = -se[0];
        float total = 0.f;
        for (int l = 0; l < LVL; l++) total += sc[l] / 8388608.0f;
        o_sc[0] = 0.25f * total;
        o_sc[1] = total;
        o_sc[2] = expf(ent);
    }
}

// ---------------- launch ----------------
extern "C" void kernel_launch(void* const* d_in, const int* in_sizes, int n_in,
                              void* d_out, int out_size)
{
    const float* z   = (const float*)d_in[0];
    const float* emb = (const float*)d_in[1];
    if (n_in >= 2 && in_sizes[0] == LVL * CBK * DIM && in_sizes[1] == BATCH * DIM) {
        emb = (const float*)d_in[0];
        z   = (const float*)d_in[1];
    }

    cudaFuncSetAttribute(k_level, cudaFuncAttributeMaxDynamicSharedMemorySize, SMEM_BYTES);

    float* out = (float*)d_out;
    const long NZQ = (long)BATCH * DIM;   // 8388608
    const long NI  = (long)BATCH * LVL;   // 262144
    float* o_zq  = ((long)out_size >= NZQ)          ? out             : nullptr;
    float* o_idx = ((long)out_size >= NZQ + NI)     ? out + NZQ       : nullptr;
    float* o_sc  = ((long)out_size >= NZQ + NI + 3) ? out + NZQ + NI  : nullptr;

    k_prepB<<<(LVL * CBK * DIM) / 256, 256>>>(emb);
    k_eeinit<<<(LVL * CBK) / 8, 256>>>(emb);
    k_prepA<<<BATCH / 8, 256>>>(z);
    for (int l = 0; l < LVL; l++)
        k_level<<<GRID, 512, SMEM_BYTES>>>(z, emb + (size_t)l * CBK * DIM, l, o_idx);
    k_count<<<64, 256>>>();
    if (o_zq) k_zq<<<2048, 256>>>(z, o_zq);
    k_final<<<1, 1024>>>(o_sc);
}

// round 14
// speedup vs baseline: 2.0458x; 2.0458x over previous
#include <cuda_runtime.h>
#include <cuda_fp16.h>
#include <math.h>
#include <stdint.h>

#define BATCH 32768
#define DIM   256
#define CBK   1024
#define LVL   8
#define BM    128
#define GRID  (BATCH / BM)           // 256
#define MUT   1.2e-3f                // >= 2B, B = hard fp16 1-pass score-error bound (~5e-4)

// smem byte offsets
#define SO_A    0                    // A tile [128 rows][256 k] fp16, 512B rows = 65536
#define SO_B    65536                // B slabs 2 x [128 codes][128 k] fp16 = 65536
#define SO_EE   131072               // 1024 floats = 4096
#define SO_CV   135168               // cand values [128 rows][48] = 24576
#define SO_CI   159744               // cand indices = 24576
#define SO_IDX  184320               // 128 ints
#define SO_RED  184832               // 512 floats = 2048
#define SO_CNT  186880               // [0]=rescue cnt, [1]=fullscan cnt (+pad)
#define SO_RQ   186896               // 128 entries x 8 ints = 4096
#define SO_FQ   190992               // 128 ints
#define SMEM_BYTES 191504

// ---------------- device scratch ----------------
__device__ float g_resid[BATCH * DIM];
__device__ float g_qsum [BATCH * DIM];
__device__ float g_xx   [BATCH];
__device__ float g_ee   [LVL * CBK];
__device__ int   g_idx  [BATCH * LVL];
__device__ float g_commit_part[LVL * GRID];
__device__ int   g_counts[CBK];
__device__ __half g_ah[BATCH * DIM];        // residual fp16
__device__ __half g_bh[LVL * CBK * DIM];    // codebook fp16

// ---------------- helpers ----------------
__device__ __forceinline__ uint32_t smem_u32(const void* p) {
    uint32_t a;
    asm("{ .reg .u64 t; cvta.to.shared.u64 t, %1; cvt.u32.u64 %0, t; }" : "=r"(a) : "l"(p));
    return a;
}
#define CP16(dst, src) asm volatile("cp.async.cg.shared.global [%0], [%1], 16;" :: "r"(dst), "l"(src))
#define CPCOMMIT()     asm volatile("cp.async.commit_group;" ::: "memory")
#define CPWAIT1()      asm volatile("cp.async.wait_group 1;" ::: "memory")
#define CPWAIT0()      asm volatile("cp.async.wait_group 0;" ::: "memory")

__device__ __forceinline__ void ldsm_x4(uint32_t* r, uint32_t addr) {
    asm volatile("ldmatrix.sync.aligned.m8n8.x4.shared.b16 {%0,%1,%2,%3}, [%4];"
        : "=r"(r[0]), "=r"(r[1]), "=r"(r[2]), "=r"(r[3]) : "r"(addr));
}
__device__ __forceinline__ void mma_f16(float* d, const uint32_t* a, const uint32_t* b) {
    asm volatile("mma.sync.aligned.m16n8k16.row.col.f32.f16.f16.f32 "
        "{%0,%1,%2,%3}, {%4,%5,%6,%7}, {%8,%9}, {%0,%1,%2,%3};"
        : "+f"(d[0]), "+f"(d[1]), "+f"(d[2]), "+f"(d[3])
        : "r"(a[0]), "r"(a[1]), "r"(a[2]), "r"(a[3]), "r"(b[0]), "r"(b[1]));
}

// ---------------- prep kernels ----------------
__global__ void k_prepB(const float* __restrict__ emb)
{
    int i = blockIdx.x * blockDim.x + threadIdx.x;
    if (i >= LVL * CBK * DIM) return;
    g_bh[i] = __float2half_rn(emb[i]);
}

__global__ void k_eeinit(const float* __restrict__ emb)
{
    int gt = blockIdx.x * blockDim.x + threadIdx.x;
    if (gt < CBK) g_counts[gt] = 0;
    int gw   = blockIdx.x * (blockDim.x >> 5) + (threadIdx.x >> 5);
    int lane = threadIdx.x & 31;
    if (gw >= LVL * CBK) return;
    const float* r = emb + (size_t)gw * DIM;
    float s = 0.f;
#pragma unroll
    for (int j = 0; j < 8; j++) { float v = r[lane + 32 * j]; s = fmaf(v, v, s); }
#pragma unroll
    for (int o = 16; o; o >>= 1) s += __shfl_xor_sync(0xffffffffu, s, o);
    if (!lane) g_ee[gw] = s;
}

__global__ void k_prepA(const float* __restrict__ z)
{
    int gw   = blockIdx.x * (blockDim.x >> 5) + (threadIdx.x >> 5);
    int lane = threadIdx.x & 31;
    if (gw >= BATCH) return;
    const float* r = z + (size_t)gw * DIM;
    float s = 0.f;
#pragma unroll
    for (int j = 0; j < 8; j++) {
        float v = r[lane + 32 * j];
        g_ah[(size_t)gw * DIM + lane + 32 * j] = __float2half_rn(v);
        s = fmaf(v, v, s);
    }
#pragma unroll
    for (int o = 16; o; o >>= 1) s += __shfl_xor_sync(0xffffffffu, s, o);
    if (!lane) g_xx[gw] = s;
}

// ---------------- main per-level kernel: fp16 1-pass HMMA + top-3/lane + 3-way ------
// 256 CTAs x 512 threads (16 warps = 4m x 4n, warp tile 32x32).
// Per-lane top-3 over its 64 codes -> 48 candidates/row in smem.
// Guard G = min lane v3 lower-bounds every uncaptured candidate.
// direct (1 cand) / exact rescue (<=6 cands, warp-parallel) / warp-per-row full scan.
__global__ void __launch_bounds__(512, 1)
k_level(const float* __restrict__ z,
        const float* __restrict__ cb,     // fp32 codebook for this level
        int level,
        float* __restrict__ o_idx_f)
{
    extern __shared__ char smem[];
    uint32_t sb = smem_u32(smem);
    float* ee_s  = (float*)(smem + SO_EE);
    float* cv    = (float*)(smem + SO_CV);
    int*   cidx  = (int*)(smem + SO_CI);
    int*   s_idx = (int*)(smem + SO_IDX);
    float* s_red = (float*)(smem + SO_RED);
    int*   s_cnt = (int*)(smem + SO_CNT);      // [0]=rescue, [1]=fullscan
    int*   rq    = (int*)(smem + SO_RQ);
    int*   fq    = (int*)(smem + SO_FQ);

    const int tid = threadIdx.x, wid = tid >> 5, lane = tid & 31;
    const int wm = wid >> 2, wn = wid & 3;
    const int row0 = blockIdx.x * BM;
    const int first = (level == 0);
    const float* A_src = first ? z : g_resid;
    const __half* pbh = g_bh + (size_t)level * CBK * DIM;

    if (tid == 0) { s_cnt[0] = 0; s_cnt[1] = 0; }

    // ---- A tile: [128 rows][256 k] fp16, 512B rows, swizzled, cp.async ----
    {
#pragma unroll
        for (int i = 0; i < 8; i++) {
            int ch = i * 512 + tid;
            int m = ch >> 5, kc = ch & 31;
            const __half* src = g_ah + (size_t)(row0 + m) * DIM + kc * 8;
            uint32_t dst = sb + SO_A + m * 512 + ((kc * 16) ^ ((m & 7) << 4));
            CP16(dst, src);
        }
        CPCOMMIT();
    }
    for (int i = tid; i < CBK; i += 512) ee_s[i] = g_ee[level * CBK + i];

    const int q2   = (lane & 3) * 2;
    const int rthr = lane >> 2;
    const int arow = ((lane >> 3) & 1) * 8 + (lane & 7);
    const int kofA = (lane >> 4) * 8;
    const int brow = ((lane >> 4) & 1) * 8 + (lane & 7);
    const int kofB = ((lane >> 3) & 1) * 8;

    uint32_t aOff[2]; int aKey[2];
#pragma unroll
    for (int im = 0; im < 2; im++) {
        int m = wm * 32 + im * 16 + arow;
        aOff[im] = sb + SO_A + m * 512;
        aKey[im] = (m & 7) << 4;
    }
    uint32_t bOff[2]; int bKey[2];
#pragma unroll
    for (int jg = 0; jg < 2; jg++) {
        int nr = wn * 32 + jg * 16 + brow;
        bOff[jg] = nr * 256;
        bKey[jg] = (nr & 7) << 4;
    }
    float xr[4];
#pragma unroll
    for (int i = 0; i < 4; i++)
        xr[i] = g_xx[row0 + wm * 32 + (i >> 1) * 16 + (i & 1) * 8 + rthr];

    float acc[2][4][4];
#pragma unroll
    for (int a = 0; a < 2; a++)
#pragma unroll
        for (int b = 0; b < 4; b++)
#pragma unroll
            for (int c = 0; c < 4; c++) acc[a][b][c] = 0.f;
    // per-lane top-3 per row-position
    float v1[4], v2[4], v3[4]; int i1[4], i2[4], i3[4];
#pragma unroll
    for (int i = 0; i < 4; i++) {
        v1[i] = 3.4e38f; v2[i] = 3.4e38f; v3[i] = 3.4e38f;
        i1[i] = 1 << 29; i2[i] = 1 << 29; i3[i] = 1 << 29;
    }

    // B slab s: codes [nt*128,+128), k [half*128,+128); 32KB, 256B swizzled rows
    auto loadB = [&](int s) {
        int nt = s >> 1, half = s & 1;
        uint32_t dB = sb + SO_B + (s & 1) * 32768;
#pragma unroll
        for (int i = 0; i < 4; i++) {
            int ch = i * 512 + tid;
            int r = ch >> 4, kc = ch & 15;
            CP16(dB + r * 256 + ((kc * 16) ^ ((r & 7) << 4)),
                 pbh + (size_t)(nt * 128 + r) * DIM + half * 128 + kc * 8);
        }
        CPCOMMIT();
    };

    loadB(0);

#define UPD(rp, dval, cx) do { \
        if ((dval) < v1[rp]) { v3[rp] = v2[rp]; i3[rp] = i2[rp]; v2[rp] = v1[rp]; i2[rp] = i1[rp]; \
                               v1[rp] = (dval); i1[rp] = (cx); } \
        else if ((dval) < v2[rp]) { v3[rp] = v2[rp]; i3[rp] = i2[rp]; v2[rp] = (dval); i2[rp] = (cx); } \
        else if ((dval) < v3[rp]) { v3[rp] = (dval); i3[rp] = (cx); } } while (0)

    // ---- mainloop: 8 N-chunks x 2 k-halves = 16 steps ----
    for (int s = 0; s < 16; s++) {
        if (s + 1 < 16) { loadB(s + 1); CPWAIT1(); } else { CPWAIT0(); }
        __syncthreads();
        int nt = s >> 1, half = s & 1;
        uint32_t bB = sb + SO_B + (s & 1) * 32768;
#pragma unroll
        for (int kc = 0; kc < 8; kc++) {
            uint32_t bf[2][4];
#pragma unroll
            for (int jg = 0; jg < 2; jg++)
                ldsm_x4(bf[jg], bB + bOff[jg] + ((((kc * 16 + kofB) << 1)) ^ bKey[jg]));
            uint32_t af[2][4];
            int kh = half * 128 + kc * 16;
#pragma unroll
            for (int im = 0; im < 2; im++)
                ldsm_x4(af[im], aOff[im] + ((((kh + kofA) << 1)) ^ aKey[im]));
#pragma unroll
            for (int im = 0; im < 2; im++) {
                mma_f16(acc[im][0], af[im], &bf[0][0]);
                mma_f16(acc[im][1], af[im], &bf[0][2]);
                mma_f16(acc[im][2], af[im], &bf[1][0]);
                mma_f16(acc[im][3], af[im], &bf[1][2]);
            }
        }
        if (half) {                                     // N-chunk done: score + top-3
#pragma unroll
            for (int im = 0; im < 2; im++)
#pragma unroll
                for (int jj = 0; jj < 4; jj++) {
                    int col = nt * 128 + wn * 32 + (jj >> 1) * 16 + (jj & 1) * 8 + q2;
                    float e0 = ee_s[col], e1 = ee_s[col + 1];
                    float d;
                    d = (xr[im * 2] + e0) - 2.0f * acc[im][jj][0];
                    UPD(im * 2, d, col);
                    d = (xr[im * 2] + e1) - 2.0f * acc[im][jj][1];
                    UPD(im * 2, d, col + 1);
                    d = (xr[im * 2 + 1] + e0) - 2.0f * acc[im][jj][2];
                    UPD(im * 2 + 1, d, col);
                    d = (xr[im * 2 + 1] + e1) - 2.0f * acc[im][jj][3];
                    UPD(im * 2 + 1, d, col + 1);
                    acc[im][jj][0] = 0.f; acc[im][jj][1] = 0.f;
                    acc[im][jj][2] = 0.f; acc[im][jj][3] = 0.f;
                }
        }
        __syncthreads();
    }

    // ---- every lane stores its top-3 (16 lanes x 3 per row, lossless to 3rd order) ----
#pragma unroll
    for (int i = 0; i < 4; i++) {
        int row = wm * 32 + (i >> 1) * 16 + (i & 1) * 8 + rthr;
        int g = (wn * 4 + (lane & 3)) * 3;
        cv[row * 48 + g]     = v1[i];  cidx[row * 48 + g]     = i1[i];
        cv[row * 48 + g + 1] = v2[i];  cidx[row * 48 + g + 1] = i2[i];
        cv[row * 48 + g + 2] = v3[i];  cidx[row * 48 + g + 2] = i3[i];
    }
    __syncthreads();

    // ---- per-row decision (thread tid = row): direct / rescue / full-scan ----
    if (tid < 128) {
        float w0 = 3.4e38f; int x0 = 1 << 30;
#pragma unroll 8
        for (int g2 = 0; g2 < 48; g2++) {
            float v = cv[tid * 48 + g2];
            int  ix = cidx[tid * 48 + g2];
            if (v < w0 || (v == w0 && ix < x0)) { w0 = v; x0 = ix; }
        }
        float G = 3.4e38f;
#pragma unroll
        for (int g2 = 2; g2 < 48; g2 += 3) G = fminf(G, cv[tid * 48 + g2]);  // lane v3s
        float T = w0 + MUT;
        if (G <= T) {
            fq[atomicAdd(&s_cnt[1], 1)] = tid;          // uncaptured candidate may be in margin
        } else {
            int n = 0, cand[6];
#pragma unroll 8
            for (int g2 = 0; g2 < 48; g2++) {
                float v = cv[tid * 48 + g2];
                if (v <= T) { if (n < 6) cand[n] = cidx[tid * 48 + g2]; n++; }
            }
            if (n > 6) {
                fq[atomicAdd(&s_cnt[1], 1)] = tid;
            } else if (n == 1) {                        // provably the reference winner
                s_idx[tid] = x0;
                int gr = row0 + tid;
                g_idx[(size_t)gr * LVL + level] = x0;
                if (o_idx_f) o_idx_f[(size_t)gr * LVL + level] = (float)x0;
            } else {                                    // exact rescue among n cands
                int pos = atomicAdd(&s_cnt[0], 1);
                rq[pos * 8 + 0] = tid;
                rq[pos * 8 + 1] = n;
#pragma unroll
                for (int q = 0; q < 6; q++) rq[pos * 8 + 2 + q] = (q < n) ? cand[q] : 0;
            }
        }
    }
    __syncthreads();

    // ---- rescue: exact fp32 sequential-k dd for <=6 candidates (warp per entry) ----
    {
        int cnt = s_cnt[0];
        for (int e = wid; e < cnt; e += 16) {
            int row = rq[e * 8], n = rq[e * 8 + 1];
            float dd = 3.4e38f; int ci = 1 << 30;
            if (lane < n) {
                ci = rq[e * 8 + 2 + lane];
                const float* a  = A_src + (size_t)(row0 + row) * DIM;
                const float* ep = cb + (size_t)ci * DIM;
                float dot = 0.f;
#pragma unroll 4
                for (int k = 0; k < 256; k++) dot = fmaf(a[k], ep[k], dot);
                dd = (g_xx[row0 + row] + ee_s[ci]) - 2.0f * dot;
            }
#pragma unroll
            for (int o = 1; o <= 4; o <<= 1) {          // reduce over 8-lane group
                float ov = __shfl_xor_sync(0xffffffffu, dd, o);
                int   oi = __shfl_xor_sync(0xffffffffu, ci, o);
                if (ov < dd || (ov == dd && oi < ci)) { dd = ov; ci = oi; }
            }
            if (lane == 0) {
                s_idx[row] = ci;
                int gr = row0 + row;
                g_idx[(size_t)gr * LVL + level] = ci;
                if (o_idx_f) o_idx_f[(size_t)gr * LVL + level] = (float)ci;
            }
        }
    }

    // ---- full-scan: warp-per-row exact 1024-code scan (rare; no barriers inside) ----
    {
        int fcnt = s_cnt[1];
        for (int e = wid; e < fcnt; e += 16) {
            int row = fq[e];
            const float* a = A_src + (size_t)(row0 + row) * DIM;
            float xxv = g_xx[row0 + row];
            float best = 3.4e38f; int bix = 1 << 30;
            for (int c = lane; c < CBK; c += 32) {
                const float* ep = cb + (size_t)c * DIM;
                float dot = 0.f;
#pragma unroll 4
                for (int k = 0; k < 256; k++) dot = fmaf(a[k], ep[k], dot);
                float dd = (xxv + ee_s[c]) - 2.0f * dot;
                if (dd < best) { best = dd; bix = c; }  // c ascending: ties keep lower
            }
#pragma unroll
            for (int o = 16; o; o >>= 1) {
                float ov = __shfl_xor_sync(0xffffffffu, best, o);
                int   oi = __shfl_xor_sync(0xffffffffu, bix, o);
                if (ov < best || (ov == best && oi < bix)) { best = ov; bix = oi; }
            }
            if (!lane) {
                s_idx[row] = bix;
                int gr = row0 + row;
                g_idx[(size_t)gr * LVL + level] = bix;
                if (o_idx_f) o_idx_f[(size_t)gr * LVL + level] = (float)bix;
            }
        }
    }
    __syncthreads();

    // ---- fused epilogue: residual, qsum, fp16 for next level, xx, commit ----
    {
        int r4 = tid >> 2, dq = (tid & 3) << 6;     // 4 threads/row, 64 dims each
        int gi = s_idx[r4];
        const float* ev = cb + (size_t)gi * DIM + dq;
        size_t gofs = (size_t)(row0 + r4) * DIM + dq;
        const float* av = A_src + gofs;
        float* ro = g_resid + gofs;
        float* qo = g_qsum + gofs;
        __half2* ho = (__half2*)(g_ah + gofs);
        float ss = 0.f;
#pragma unroll 4
        for (int j = 0; j < 16; j++) {
            float4 a = *(const float4*)(av + j * 4);
            float4 e = *(const float4*)(ev + j * 4);
            float4 rn = make_float4(a.x - e.x, a.y - e.y, a.z - e.z, a.w - e.w);
            *(float4*)(ro + j * 4) = rn;
            float4 q;
            if (first) q = e;
            else {
                float4 qp = *(const float4*)(qo + j * 4);
                q = make_float4(qp.x + e.x, qp.y + e.y, qp.z + e.z, qp.w + e.w);
            }
            *(float4*)(qo + j * 4) = q;
            ho[j * 2]     = __floats2half2_rn(rn.x, rn.y);
            ho[j * 2 + 1] = __floats2half2_rn(rn.z, rn.w);
            ss = fmaf(rn.x, rn.x, ss); ss = fmaf(rn.y, rn.y, ss);
            ss = fmaf(rn.z, rn.z, ss); ss = fmaf(rn.w, rn.w, ss);
        }
        s_red[tid] = ss;
        __syncthreads();
        if (!(tid & 3))
            g_xx[row0 + r4] = (s_red[tid] + s_red[tid + 1]) + (s_red[tid + 2] + s_red[tid + 3]);
        __syncthreads();
#pragma unroll
        for (int o = 256; o; o >>= 1) {
            if (tid < o) s_red[tid] += s_red[tid + o];
            __syncthreads();
        }
        if (!tid) g_commit_part[level * GRID + blockIdx.x] = s_red[0];
    }
#undef UPD
}

// ---------------- histogram ----------------
__global__ void k_count()
{
    __shared__ int h[CBK];
    for (int i = threadIdx.x; i < CBK; i += blockDim.x) h[i] = 0;
    __syncthreads();
    int stride = gridDim.x * blockDim.x;
    for (int i = blockIdx.x * blockDim.x + threadIdx.x; i < BATCH * LVL; i += stride)
        atomicAdd(&h[g_idx[i]], 1);
    __syncthreads();
    for (int i = threadIdx.x; i < CBK; i += blockDim.x) {
        int v = h[i];
        if (v) atomicAdd(&g_counts[i], v);
    }
}

// ---------------- z_q ----------------
__global__ void k_zq(const float* __restrict__ z, float* __restrict__ out)
{
    int n = BATCH * DIM / 4;
    for (int i = blockIdx.x * blockDim.x + threadIdx.x; i < n; i += gridDim.x * blockDim.x) {
        float4 zv = ((const float4*)z)[i];
        float4 qv = ((const float4*)g_qsum)[i];
        float4 t = make_float4(qv.x - zv.x, qv.y - zv.y, qv.z - zv.z, qv.w - zv.w);
        ((float4*)out)[i] = make_float4(zv.x + t.x, zv.y + t.y, zv.z + t.z, zv.w + t.w);
    }
}

// ---------------- scalars ----------------
__global__ void k_final(float* __restrict__ o_sc)
{
    __shared__ float se[1024];
    __shared__ float sc[LVL];
    int t = threadIdx.x;
    float p = (float)g_counts[t] / 262144.0f;
    se[t] = (p > 0.f) ? p * logf(p + 1e-10f) : 0.f;
    __syncthreads();
#pragma unroll
    for (int o = 512; o; o >>= 1) {
        if (t < o) se[t] += se[t + o];
        __syncthreads();
    }
    int w = t >> 5, lane = t & 31;
    if (w < LVL) {
        float s = 0.f;
        for (int b = lane; b < GRID; b += 32) s += g_commit_part[w * GRID + b];
#pragma unroll
        for (int o = 16; o; o >>= 1) s += __shfl_xor_sync(0xffffffffu, s, o);
        if (!lane) sc[w] = s;
    }
    __syncthreads();
    if (!t && o_sc) {
        float ent = -se[0];
        float total = 0.f;
        for (int l = 0; l < LVL; l++) total += sc[l] / 8388608.0f;
        o_sc[0] = 0.25f * total;
        o_sc[1] = total;
        o_sc[2] = expf(ent);
    }
}

// ---------------- launch ----------------
extern "C" void kernel_launch(void* const* d_in, const int* in_sizes, int n_in,
                              void* d_out, int out_size)
{
    const float* z   = (const float*)d_in[0];
    const float* emb = (const float*)d_in[1];
    if (n_in >= 2 && in_sizes[0] == LVL * CBK * DIM && in_sizes[1] == BATCH * DIM) {
        emb = (const float*)d_in[0];
        z   = (const float*)d_in[1];
    }

    cudaFuncSetAttribute(k_level, cudaFuncAttributeMaxDynamicSharedMemorySize, SMEM_BYTES);

    float* out = (float*)d_out;
    const long NZQ = (long)BATCH * DIM;   // 8388608
    const long NI  = (long)BATCH * LVL;   // 262144
    float* o_zq  = ((long)out_size >= NZQ)          ? out             : nullptr;
    float* o_idx = ((long)out_size >= NZQ + NI)     ? out + NZQ       : nullptr;
    float* o_sc  = ((long)out_size >= NZQ + NI + 3) ? out + NZQ + NI  : nullptr;

    k_prepB<<<(LVL * CBK * DIM) / 256, 256>>>(emb);
    k_eeinit<<<(LVL * CBK) / 8, 256>>>(emb);
    k_prepA<<<BATCH / 8, 256>>>(z);
    for (int l = 0; l < LVL; l++)
        k_level<<<GRID, 512, SMEM_BYTES>>>(z, emb + (size_t)l * CBK * DIM, l, o_idx);
    k_count<<<64, 256>>>();
    if (o_zq) k_zq<<<2048, 256>>>(z, o_zq);
    k_final<<<1, 1024>>>(o_sc);
}